// round 14
// baseline (speedup 1.0000x reference)
#include <cuda_runtime.h>
#include <cuda_fp16.h>
#include <math.h>
#include <stdint.h>

// ---------------- problem constants ----------------
#define CDIM   192
#define HEADS  8
#define HD     24
#define NTOK   64
#define BATCH  4
#define HIMG   256
#define WIMG   256
#define NWX    32
#define NW     1024
#define BWIN   4096
#define TPIX   262144
#define CMID   768
#define QSCALE 0.20412414523193154f
#define LN_EPS 1e-5f

#define LN_SMEM_BYTES ((CDIM*128 + 2*CDIM)*4)

// ---------------- scratch ----------------
__device__ __half g_hwin[(size_t)TPIX*CDIM];
__device__ float g_q[(size_t)BWIN*HEADS*NTOK*HD];
__device__ float g_k[(size_t)BWIN*HEADS*NTOK*HD];
__device__ float g_v[(size_t)BWIN*HEADS*NTOK*HD];
__device__ __half g_att[(size_t)TPIX*CDIM];
__device__ float g_proj[(size_t)TPIX*CDIM];
__device__ float g_xh[(size_t)TPIX*CDIM];
__device__ __half g_h2[(size_t)TPIX*CDIM];
__device__ __half g_mid[(size_t)TPIX*CMID];
__device__ float g_y[(size_t)TPIX*CDIM];

// transposed weights [N][K], fp16
__device__ __half g_wqkv[576*192];
__device__ __half g_wprj[192*192];
__device__ __half g_wfc1[768*192];
__device__ __half g_wfc2[192*768];

// ---------------- helpers ----------------
__device__ __forceinline__ uint32_t smem_u32(const void* p){
    uint32_t a;
    asm("{ .reg .u64 t; cvta.to.shared.u64 t, %1; cvt.u32.u64 %0, t; }" : "=r"(a) : "l"(p));
    return a;
}
__device__ __forceinline__ void cp_async16(uint32_t dst, const void* src){
    asm volatile("cp.async.cg.shared.global [%0], [%1], 16;" :: "r"(dst), "l"(src));
}
__device__ __forceinline__ void ldsm_x4(uint32_t* r, uint32_t addr){
    asm volatile("ldmatrix.sync.aligned.m8n8.x4.shared.b16 {%0,%1,%2,%3}, [%4];"
        : "=r"(r[0]), "=r"(r[1]), "=r"(r[2]), "=r"(r[3]) : "r"(addr));
}
__device__ __forceinline__ void mma16816(float* d, const uint32_t* a,
                                         uint32_t b0, uint32_t b1){
    asm volatile("mma.sync.aligned.m16n8k16.row.col.f32.f16.f16.f32 "
        "{%0,%1,%2,%3}, {%4,%5,%6,%7}, {%8,%9}, {%0,%1,%2,%3};"
        : "+f"(d[0]), "+f"(d[1]), "+f"(d[2]), "+f"(d[3])
        : "r"(a[0]), "r"(a[1]), "r"(a[2]), "r"(a[3]), "r"(b0), "r"(b1));
}

// ============ weight transpose: w[K][N] fp32 -> wh[N][K] fp16 ============
__global__ void wtrans_kernel(const float* __restrict__ w,
    __half* __restrict__ wh, int K, int N)
{
    __shared__ float t[32][33];
    const int tx = threadIdx.x, ty = threadIdx.y;   // (32, 8)
    const int n0 = blockIdx.x*32, k0 = blockIdx.y*32;
    #pragma unroll
    for (int j=0;j<4;j++)
        t[ty+8*j][tx] = w[(size_t)(k0+ty+8*j)*N + n0 + tx];
    __syncthreads();
    #pragma unroll
    for (int j=0;j<4;j++){
        const int n = ty + 8*j;
        wh[(size_t)(n0+n)*K + k0 + tx] = __float2half_rn(t[tx][n]);
    }
}

// ============ kernel 1: LN1 + roll(-4,-4) + window partition (fp16 out) ============
__global__ void __launch_bounds__(128) ln1_partition_kernel(
    const float* __restrict__ x, const float* __restrict__ g, const float* __restrict__ b)
{
    extern __shared__ float s[];
    float* sg = s + CDIM*128;
    float* sb = sg + CDIM;
    const int tid = threadIdx.x;
    const int w0 = blockIdx.x*128, h = blockIdx.y, bb = blockIdx.z;
    for (int i = tid; i < CDIM; i += 128){ sg[i]=g[i]; sb[i]=b[i]; }
    const float* xp = x + (size_t)bb*CDIM*HIMG*WIMG + (size_t)h*WIMG + w0;
    #pragma unroll 4
    for (int c=0;c<CDIM;c++) s[c*128+tid] = xp[(size_t)c*(HIMG*WIMG)+tid];
    __syncthreads();
    float sum=0.f, sq=0.f;
    for (int c=0;c<CDIM;c++){ float v=s[c*128+tid]; sum+=v; sq+=v*v; }
    const float mean = sum*(1.f/CDIM);
    const float var  = sq*(1.f/CDIM) - mean*mean;
    const float rstd = rsqrtf(var + LN_EPS);
    const int w  = w0 + tid;
    const int hr = (h-4)&255, wr = (w-4)&255;
    const int win = bb*NW + (hr>>3)*NWX + (wr>>3);
    const size_t base = ((size_t)win*NTOK + ((hr&7)<<3) + (wr&7))*CDIM;
    for (int c=0;c<CDIM;c++)
        g_hwin[base+c] = __float2half_rn((s[c*128+tid]-mean)*rstd*sg[c] + sb[c]);
}

// ============ HMMA fp16 single-pass GEMM, block 256x64, BK=32, warp tile 64x32 ============
// smem rows: 64B data + 16B pad per row -> conflict-free ldmatrix, aligned cp.async.
#define RPAD 80
#define CH_A (256*RPAD)            // 20480 B per stage
#define CH_B (64*RPAD)             // 5120  B per stage
#define STG  (CH_A + CH_B)         // 25600 B per stage
#define NSTAGE 3
#define SMEM_MMA (NSTAGE*STG)      // 76800 B

__device__ __forceinline__ void stage_load(uint32_t sb,
    const __half* __restrict__ A, const __half* __restrict__ Bw,
    int m0, int n0, int K, int k0, int tid)
{
    #pragma unroll
    for (int i=0;i<4;i++){
        const int cid = tid + i*256;             // 0..1023
        const int row = cid>>2, c = cid&3;
        const uint32_t off = (uint32_t)(row*RPAD + c*16);
        cp_async16(sb + off, A + (size_t)(m0+row)*K + k0 + c*8);
    }
    {
        const int row = tid>>2, c = tid&3;       // 64 rows x 4 chunks
        const uint32_t off = (uint32_t)(row*RPAD + c*16);
        cp_async16(sb + CH_A + off, Bw + (size_t)(n0+row)*K + k0 + c*8);
    }
    asm volatile("cp.async.commit_group;" ::: "memory");
}

// EPI: 0 = qkv split (+q scale), 1 = plain fp32, 2 = GELU -> fp16, 3 = residual add
template<int EPI>
__global__ void __launch_bounds__(256,2) mma_gemm(
    const __half* __restrict__ A, const __half* __restrict__ Bw,
    const float* __restrict__ bias,
    float* __restrict__ o0, float* __restrict__ o1, float* __restrict__ o2,
    const float* __restrict__ res, int K, int Ncols)
{
    extern __shared__ __align__(16) char dsm[];
    const uint32_t sbase = smem_u32(dsm);
    const int tid = threadIdx.x;
    const int wid = tid >> 5, lane = tid & 31;
    const int wm = wid >> 1, wn = wid & 1;       // 4 x 2 warp grid
    const int m0 = blockIdx.y * 256;
    const int n0 = blockIdx.x * 64;

    float acc[4][4][4];
    #pragma unroll
    for (int mi=0;mi<4;mi++)
        #pragma unroll
        for (int nj=0;nj<4;nj++)
            #pragma unroll
            for (int e=0;e<4;e++) acc[mi][nj][e]=0.f;

    const int off16 = lane & 15;
    const int khalf = lane >> 4;                 // +16B for k8..15 quads
    uint32_t aoff[4], boff[2];
    #pragma unroll
    for (int mi=0;mi<4;mi++)
        aoff[mi] = (uint32_t)((wm*64 + mi*16 + off16)*RPAD);
    #pragma unroll
    for (int j=0;j<2;j++)
        boff[j] = (uint32_t)((wn*32 + j*16 + off16)*RPAD);

    const int nch = K >> 5;                      // BK = 32
    stage_load(sbase, A, Bw, m0, n0, K, 0, tid);
    if (nch > 1)
        stage_load(sbase + STG, A, Bw, m0, n0, K, 32, tid);

    int st = 0;
    for (int kc=0; kc<nch; kc++){
        if (kc+2 < nch){
            int ps = st+2; if (ps >= NSTAGE) ps -= NSTAGE;
            stage_load(sbase + ps*STG, A, Bw, m0, n0, K, (kc+2)*32, tid);
            asm volatile("cp.async.wait_group 2;" ::: "memory");
        } else if (kc+1 < nch){
            asm volatile("cp.async.wait_group 1;" ::: "memory");
        } else {
            asm volatile("cp.async.wait_group 0;" ::: "memory");
        }
        __syncthreads();

        const uint32_t sb = sbase + st*STG;
        #pragma unroll
        for (int kk=0; kk<2; kk++){              // 2 k16 steps per BK=32
            const uint32_t cb = (uint32_t)((kk*2 + khalf)*16);
            uint32_t ah[4][4];
            #pragma unroll
            for (int mi=0;mi<4;mi++)
                ldsm_x4(ah[mi], sb + aoff[mi] + cb);
            #pragma unroll
            for (int j=0;j<2;j++){
                uint32_t bh[4];
                ldsm_x4(bh, sb + CH_A + boff[j] + cb);
                #pragma unroll
                for (int mi=0;mi<4;mi++){
                    mma16816(acc[mi][j*2+0], ah[mi], bh[0], bh[2]);
                    mma16816(acc[mi][j*2+1], ah[mi], bh[1], bh[3]);
                }
            }
        }
        __syncthreads();
        if (++st == NSTAGE) st = 0;
    }

    // ---- epilogue ----
    #pragma unroll
    for (int mi=0;mi<4;mi++){
        const int r0 = m0 + wm*64 + mi*16 + (lane>>2);
        #pragma unroll
        for (int nj=0;nj<4;nj++){
            const int c = n0 + wn*32 + nj*8 + (lane&3)*2;
            const float b0 = bias[c], b1 = bias[c+1];
            #pragma unroll
            for (int half=0; half<2; half++){
                const int row = r0 + half*8;
                float v0 = acc[mi][nj][half*2+0] + b0;
                float v1 = acc[mi][nj][half*2+1] + b1;
                if (EPI == 0){
                    const int qi   = c / CDIM;
                    const int rem  = c - qi*CDIM;
                    const int head = rem / HD, hd = rem - head*HD;
                    const int win  = row >> 6, tok = row & 63;
                    const size_t dst = (((size_t)win*HEADS + head)*NTOK + tok)*HD + hd;
                    if (qi==0){      o0[dst] = v0*QSCALE; o0[dst+1] = v1*QSCALE; }
                    else if (qi==1){ o1[dst] = v0;        o1[dst+1] = v1; }
                    else{            o2[dst] = v0;        o2[dst+1] = v1; }
                } else if (EPI == 1){
                    const size_t idx = (size_t)row*Ncols + c;
                    o0[idx]   = v0;
                    o0[idx+1] = v1;
                } else if (EPI == 2){
                    const size_t idx = (size_t)row*Ncols + c;
                    const float g0 = 0.5f*v0*(1.f + erff(v0*0.70710678118654752f));
                    const float g1 = 0.5f*v1*(1.f + erff(v1*0.70710678118654752f));
                    __half2 t2; t2.x = __float2half_rn(g0); t2.y = __float2half_rn(g1);
                    *reinterpret_cast<__half2*>((__half*)o0 + idx) = t2;
                } else {
                    const size_t idx = (size_t)row*Ncols + c;
                    o0[idx]   = res[idx]   + v0;
                    o0[idx+1] = res[idx+1] + v1;
                }
            }
        }
    }
}

// ============ kernel 3: windowed attention, one block per (window, head) ============
__global__ void __launch_bounds__(64) attn_kernel(const float* __restrict__ rpb)
{
    __shared__ float sk[NTOK*HD];
    __shared__ float sv[NTOK*HD];
    __shared__ float srp[225];
    __shared__ float Ss[NTOK*64];
    const int blk = blockIdx.x;
    const int win = blk >> 3, head = blk & 7;
    const int tid = threadIdx.x;
    const size_t base = (size_t)blk * (NTOK*HD);
    for (int i=tid;i<NTOK*HD;i+=64){ sk[i]=g_k[base+i]; sv[i]=g_v[base+i]; }
    for (int i=tid;i<225;i+=64) srp[i] = rpb[(size_t)i*HEADS + head];

    float qreg[24];
    {
        const float4* qp = reinterpret_cast<const float4*>(&g_q[base + (size_t)tid*HD]);
        #pragma unroll
        for (int i=0;i<6;i++){
            float4 t = qp[i];
            qreg[4*i]=t.x; qreg[4*i+1]=t.y; qreg[4*i+2]=t.z; qreg[4*i+3]=t.w;
        }
    }
    __syncthreads();

    const int wrow = (win & (NW-1)) >> 5;
    const int wcol = win & 31;
    const int r1 = tid >> 3, c1 = tid & 7;

    float mx = -1e30f;
    #pragma unroll 4
    for (int m=0;m<NTOK;m++){
        float s = 0.f;
        #pragma unroll
        for (int d=0;d<24;d++) s += qreg[d]*sk[m*24+d];
        const int r2 = m>>3, c2 = m&7;
        s += srp[(r1-r2+7)*15 + (c1-c2+7)];
        const bool masked = (wrow==31 && ((r1>>2)!=(r2>>2))) ||
                            (wcol==31 && ((c1>>2)!=(c2>>2)));
        if (masked) s -= 100.f;
        Ss[m*64+tid] = s;
        mx = fmaxf(mx, s);
    }
    float sum = 0.f;
    #pragma unroll 4
    for (int m=0;m<NTOK;m++){
        float e = __expf(Ss[m*64+tid] - mx);
        Ss[m*64+tid] = e;
        sum += e;
    }
    const float inv = 1.f/sum;
    float o[24];
    #pragma unroll
    for (int d=0;d<24;d++) o[d]=0.f;
    #pragma unroll 4
    for (int m=0;m<NTOK;m++){
        const float p = Ss[m*64+tid]*inv;
        #pragma unroll
        for (int d=0;d<24;d++) o[d] += p*sv[m*24+d];
    }
    const size_t ob = ((size_t)win*NTOK + tid)*CDIM + head*HD;
    #pragma unroll
    for (int i=0;i<12;i++){
        __half2 t2;
        t2.x = __float2half_rn(o[2*i]);
        t2.y = __float2half_rn(o[2*i+1]);
        *reinterpret_cast<__half2*>(&g_att[ob + 2*i]) = t2;
    }
}

// ============ kernel 5: window reverse + roll(+4,+4) + residual + LN2 ============
__global__ void __launch_bounds__(128) postattn_kernel(
    const float* __restrict__ x, const float* __restrict__ g, const float* __restrict__ b)
{
    extern __shared__ float s[];
    float* sg = s + CDIM*128;
    float* sb = sg + CDIM;
    const int tid = threadIdx.x;
    const int w0 = blockIdx.x*128, h = blockIdx.y, bb = blockIdx.z;
    for (int i=tid;i<CDIM;i+=128){ sg[i]=g[i]; sb[i]=b[i]; }
    const float* xp = x + (size_t)bb*CDIM*HIMG*WIMG + (size_t)h*WIMG + w0;
    #pragma unroll 4
    for (int c=0;c<CDIM;c++) s[c*128+tid] = xp[(size_t)c*(HIMG*WIMG)+tid];
    __syncthreads();
    const int w  = w0 + tid;
    const int hr = (h-4)&255, wr = (w-4)&255;
    const int win = bb*NW + (hr>>3)*NWX + (wr>>3);
    const size_t pbase = ((size_t)win*NTOK + ((hr&7)<<3) + (wr&7))*CDIM;
    float sum=0.f, sq=0.f;
    for (int c=0;c<CDIM;c++){
        float v = s[c*128+tid] + g_proj[pbase+c];
        s[c*128+tid] = v; sum += v; sq += v*v;
    }
    const float mean = sum*(1.f/CDIM);
    const float var  = sq*(1.f/CDIM) - mean*mean;
    const float rstd = rsqrtf(var + LN_EPS);
    const size_t ob = (((size_t)bb*HIMG + h)*WIMG + w)*CDIM;
    for (int c=0;c<CDIM;c++){
        const float v = s[c*128+tid];
        g_xh[ob+c] = v;
        g_h2[ob+c] = __float2half_rn((v-mean)*rstd*sg[c] + sb[c]);
    }
}

// ============ kernel 8: BHWC -> BCHW output transpose ============
__global__ void out_transpose_kernel(float* __restrict__ out)
{
    __shared__ float t[32][33];
    const int tx = threadIdx.x, ty = threadIdx.y;   // (32, 8)
    const int w0 = blockIdx.x*32, h = blockIdx.y, bb = blockIdx.z;
    const size_t trow = ((size_t)bb*HIMG + h)*WIMG + w0;
    for (int c0=0;c0<CDIM;c0+=32){
        #pragma unroll
        for (int j=0;j<4;j++){
            int wl = ty + j*8;
            t[wl][tx] = g_y[(trow+wl)*CDIM + c0 + tx];
        }
        __syncthreads();
        #pragma unroll
        for (int j=0;j<4;j++){
            int cl = ty + j*8;
            out[(((size_t)bb*CDIM + c0+cl)*HIMG + h)*WIMG + w0 + tx] = t[tx][cl];
        }
        __syncthreads();
    }
}

// ============ launch ============
extern "C" void kernel_launch(void* const* d_in, const int* in_sizes, int n_in,
                              void* d_out, int out_size)
{
    (void)in_sizes; (void)n_in; (void)out_size;
    const float* x      = (const float*)d_in[0];
    const float* n1g    = (const float*)d_in[1];
    const float* n1b    = (const float*)d_in[2];
    const float* qkv_w  = (const float*)d_in[3];
    const float* qkv_b  = (const float*)d_in[4];
    const float* proj_w = (const float*)d_in[5];
    const float* proj_b = (const float*)d_in[6];
    const float* rpb    = (const float*)d_in[7];
    const float* n2g    = (const float*)d_in[8];
    const float* n2b    = (const float*)d_in[9];
    const float* fc1_w  = (const float*)d_in[10];
    const float* fc1_b  = (const float*)d_in[11];
    const float* fc2_w  = (const float*)d_in[12];
    const float* fc2_b  = (const float*)d_in[13];
    float* out = (float*)d_out;

    __half *hw,*at,*h2,*md,*wq,*wp,*w1,*w2;
    float *q,*k,*v,*proj,*xh,*y;
    cudaGetSymbolAddress((void**)&hw,  g_hwin);
    cudaGetSymbolAddress((void**)&q,   g_q);
    cudaGetSymbolAddress((void**)&k,   g_k);
    cudaGetSymbolAddress((void**)&v,   g_v);
    cudaGetSymbolAddress((void**)&at,  g_att);
    cudaGetSymbolAddress((void**)&proj,g_proj);
    cudaGetSymbolAddress((void**)&xh,  g_xh);
    cudaGetSymbolAddress((void**)&h2,  g_h2);
    cudaGetSymbolAddress((void**)&md,  g_mid);
    cudaGetSymbolAddress((void**)&y,   g_y);
    cudaGetSymbolAddress((void**)&wq,  g_wqkv);
    cudaGetSymbolAddress((void**)&wp,  g_wprj);
    cudaGetSymbolAddress((void**)&w1,  g_wfc1);
    cudaGetSymbolAddress((void**)&w2,  g_wfc2);

    cudaFuncSetAttribute(ln1_partition_kernel,
        cudaFuncAttributeMaxDynamicSharedMemorySize, LN_SMEM_BYTES);
    cudaFuncSetAttribute(postattn_kernel,
        cudaFuncAttributeMaxDynamicSharedMemorySize, LN_SMEM_BYTES);
    cudaFuncSetAttribute(mma_gemm<0>,
        cudaFuncAttributeMaxDynamicSharedMemorySize, SMEM_MMA);
    cudaFuncSetAttribute(mma_gemm<1>,
        cudaFuncAttributeMaxDynamicSharedMemorySize, SMEM_MMA);
    cudaFuncSetAttribute(mma_gemm<2>,
        cudaFuncAttributeMaxDynamicSharedMemorySize, SMEM_MMA);
    cudaFuncSetAttribute(mma_gemm<3>,
        cudaFuncAttributeMaxDynamicSharedMemorySize, SMEM_MMA);

    const dim3 wt(32,8);
    // 0. pre-transpose weights to [N][K] fp16
    wtrans_kernel<<<dim3(576/32, 192/32), wt>>>(qkv_w, wq, CDIM, 3*CDIM);
    wtrans_kernel<<<dim3(192/32, 192/32), wt>>>(proj_w, wp, CDIM, CDIM);
    wtrans_kernel<<<dim3(768/32, 192/32), wt>>>(fc1_w, w1, CDIM, CMID);
    wtrans_kernel<<<dim3(192/32, 768/32), wt>>>(fc2_w, w2, CMID, CDIM);

    const dim3 lnGrid(WIMG/128, HIMG, BATCH);

    // 1. LN1 + roll + window partition (fp16)
    ln1_partition_kernel<<<lnGrid, 128, LN_SMEM_BYTES>>>(x, n1g, n1b);

    // 2. qkv GEMM: (262144 x 192) @ (192 x 576), split q/k/v, q pre-scaled
    mma_gemm<0><<<dim3(9, TPIX/256), 256, SMEM_MMA>>>(
        hw, wq, qkv_b, q, k, v, nullptr, CDIM, 3*CDIM);

    // 3. attention per (window, head) -> fp16
    attn_kernel<<<BWIN*HEADS, 64>>>(rpb);

    // 4. proj GEMM: (262144 x 192) @ (192 x 192)
    mma_gemm<1><<<dim3(3, TPIX/256), 256, SMEM_MMA>>>(
        at, wp, proj_b, proj, nullptr, nullptr, nullptr, CDIM, CDIM);

    // 5. window reverse + roll + residual + LN2 (h2 as fp16)
    postattn_kernel<<<lnGrid, 128, LN_SMEM_BYTES>>>(x, n2g, n2b);

    // 6. fc1 GEMM: (262144 x 192) @ (192 x 768) + GELU -> fp16
    mma_gemm<2><<<dim3(12, TPIX/256), 256, SMEM_MMA>>>(
        h2, w1, fc1_b, (float*)md, nullptr, nullptr, nullptr, CDIM, CMID);

    // 7. fc2 GEMM: (262144 x 768) @ (768 x 192) + residual
    mma_gemm<3><<<dim3(3, TPIX/256), 256, SMEM_MMA>>>(
        md, w2, fc2_b, y, nullptr, nullptr, xh, CMID, CDIM);

    // 8. BHWC -> BCHW
    out_transpose_kernel<<<dim3(WIMG/32, HIMG, BATCH), dim3(32,8)>>>(out);
}

// round 15
// speedup vs baseline: 1.0017x; 1.0017x over previous
#include <cuda_runtime.h>
#include <cuda_fp16.h>
#include <math.h>
#include <stdint.h>

// ---------------- problem constants ----------------
#define CDIM   192
#define HEADS  8
#define HD     24
#define NTOK   64
#define BATCH  4
#define HIMG   256
#define WIMG   256
#define NWX    32
#define NW     1024
#define BWIN   4096
#define TPIX   262144
#define CMID   768
#define QSCALE 0.20412414523193154f
#define LN_EPS 1e-5f

#define LN_SMEM_BYTES ((CDIM*128 + 2*CDIM)*4)

// ---------------- scratch ----------------
__device__ __half g_hwin[(size_t)TPIX*CDIM];
__device__ float g_q[(size_t)BWIN*HEADS*NTOK*HD];
__device__ float g_k[(size_t)BWIN*HEADS*NTOK*HD];
__device__ float g_v[(size_t)BWIN*HEADS*NTOK*HD];
__device__ __half g_att[(size_t)TPIX*CDIM];
__device__ float g_proj[(size_t)TPIX*CDIM];
__device__ float g_xh[(size_t)TPIX*CDIM];
__device__ __half g_h2[(size_t)TPIX*CDIM];
__device__ __half g_mid[(size_t)TPIX*CMID];
__device__ float g_y[(size_t)TPIX*CDIM];

// transposed weights [N][K], fp16
__device__ __half g_wqkv[576*192];
__device__ __half g_wprj[192*192];
__device__ __half g_wfc1[768*192];
__device__ __half g_wfc2[192*768];

// ---------------- helpers ----------------
__device__ __forceinline__ uint32_t smem_u32(const void* p){
    uint32_t a;
    asm("{ .reg .u64 t; cvta.to.shared.u64 t, %1; cvt.u32.u64 %0, t; }" : "=r"(a) : "l"(p));
    return a;
}
__device__ __forceinline__ void cp_async16(uint32_t dst, const void* src){
    asm volatile("cp.async.cg.shared.global [%0], [%1], 16;" :: "r"(dst), "l"(src));
}
__device__ __forceinline__ void ldsm_x4(uint32_t* r, uint32_t addr){
    asm volatile("ldmatrix.sync.aligned.m8n8.x4.shared.b16 {%0,%1,%2,%3}, [%4];"
        : "=r"(r[0]), "=r"(r[1]), "=r"(r[2]), "=r"(r[3]) : "r"(addr));
}
__device__ __forceinline__ void mma16816(float* d, const uint32_t* a,
                                         uint32_t b0, uint32_t b1){
    asm volatile("mma.sync.aligned.m16n8k16.row.col.f32.f16.f16.f32 "
        "{%0,%1,%2,%3}, {%4,%5,%6,%7}, {%8,%9}, {%0,%1,%2,%3};"
        : "+f"(d[0]), "+f"(d[1]), "+f"(d[2]), "+f"(d[3])
        : "r"(a[0]), "r"(a[1]), "r"(a[2]), "r"(a[3]), "r"(b0), "r"(b1));
}

// ============ weight transpose: w[K][N] fp32 -> wh[N][K] fp16 ============
__global__ void wtrans_kernel(const float* __restrict__ w,
    __half* __restrict__ wh, int K, int N)
{
    __shared__ float t[32][33];
    const int tx = threadIdx.x, ty = threadIdx.y;   // (32, 8)
    const int n0 = blockIdx.x*32, k0 = blockIdx.y*32;
    #pragma unroll
    for (int j=0;j<4;j++)
        t[ty+8*j][tx] = w[(size_t)(k0+ty+8*j)*N + n0 + tx];
    __syncthreads();
    #pragma unroll
    for (int j=0;j<4;j++){
        const int n = ty + 8*j;
        wh[(size_t)(n0+n)*K + k0 + tx] = __float2half_rn(t[tx][n]);
    }
}

// ============ kernel 1: LN1 + roll(-4,-4) + window partition (fp16 out) ============
__global__ void __launch_bounds__(128) ln1_partition_kernel(
    const float* __restrict__ x, const float* __restrict__ g, const float* __restrict__ b)
{
    extern __shared__ float s[];
    float* sg = s + CDIM*128;
    float* sb = sg + CDIM;
    const int tid = threadIdx.x;
    const int w0 = blockIdx.x*128, h = blockIdx.y, bb = blockIdx.z;
    for (int i = tid; i < CDIM; i += 128){ sg[i]=g[i]; sb[i]=b[i]; }
    const float* xp = x + (size_t)bb*CDIM*HIMG*WIMG + (size_t)h*WIMG + w0;
    #pragma unroll 4
    for (int c=0;c<CDIM;c++) s[c*128+tid] = xp[(size_t)c*(HIMG*WIMG)+tid];
    __syncthreads();
    float sum=0.f, sq=0.f;
    for (int c=0;c<CDIM;c++){ float v=s[c*128+tid]; sum+=v; sq+=v*v; }
    const float mean = sum*(1.f/CDIM);
    const float var  = sq*(1.f/CDIM) - mean*mean;
    const float rstd = rsqrtf(var + LN_EPS);
    const int w  = w0 + tid;
    const int hr = (h-4)&255, wr = (w-4)&255;
    const int win = bb*NW + (hr>>3)*NWX + (wr>>3);
    const size_t base = ((size_t)win*NTOK + ((hr&7)<<3) + (wr&7))*CDIM;
    for (int c=0;c<CDIM;c++)
        g_hwin[base+c] = __float2half_rn((s[c*128+tid]-mean)*rstd*sg[c] + sb[c]);
}

// ============ HMMA fp16 single-pass GEMM, block 256x64, BK=32, warp tile 64x32 ============
// smem rows: 64B data + 16B pad per row -> conflict-free ldmatrix, aligned cp.async.
#define RPAD 80
#define CH_A (256*RPAD)            // 20480 B per stage
#define CH_B (64*RPAD)             // 5120  B per stage
#define STG  (CH_A + CH_B)         // 25600 B per stage
#define NSTAGE 3
#define SMEM_MMA (NSTAGE*STG)      // 76800 B

__device__ __forceinline__ void stage_load(uint32_t sb,
    const __half* __restrict__ A, const __half* __restrict__ Bw,
    int m0, int n0, int K, int k0, int tid)
{
    #pragma unroll
    for (int i=0;i<4;i++){
        const int cid = tid + i*256;             // 0..1023
        const int row = cid>>2, c = cid&3;
        const uint32_t off = (uint32_t)(row*RPAD + c*16);
        cp_async16(sb + off, A + (size_t)(m0+row)*K + k0 + c*8);
    }
    {
        const int row = tid>>2, c = tid&3;       // 64 rows x 4 chunks
        const uint32_t off = (uint32_t)(row*RPAD + c*16);
        cp_async16(sb + CH_A + off, Bw + (size_t)(n0+row)*K + k0 + c*8);
    }
    asm volatile("cp.async.commit_group;" ::: "memory");
}

// EPI: 0 = qkv split (+q scale), 1 = plain fp32, 2 = GELU -> fp16, 3 = residual add
template<int EPI>
__global__ void __launch_bounds__(256,2) mma_gemm(
    const __half* __restrict__ A, const __half* __restrict__ Bw,
    const float* __restrict__ bias,
    float* __restrict__ o0, float* __restrict__ o1, float* __restrict__ o2,
    const float* __restrict__ res, int K, int Ncols)
{
    extern __shared__ __align__(16) char dsm[];
    const uint32_t sbase = smem_u32(dsm);
    const int tid = threadIdx.x;
    const int wid = tid >> 5, lane = tid & 31;
    const int wm = wid >> 1, wn = wid & 1;       // 4 x 2 warp grid
    const int m0 = blockIdx.y * 256;
    const int n0 = blockIdx.x * 64;

    float acc[4][4][4];
    #pragma unroll
    for (int mi=0;mi<4;mi++)
        #pragma unroll
        for (int nj=0;nj<4;nj++)
            #pragma unroll
            for (int e=0;e<4;e++) acc[mi][nj][e]=0.f;

    const int off16 = lane & 15;
    const int khalf = lane >> 4;                 // +16B for k8..15 quads
    uint32_t aoff[4], boff[2];
    #pragma unroll
    for (int mi=0;mi<4;mi++)
        aoff[mi] = (uint32_t)((wm*64 + mi*16 + off16)*RPAD);
    #pragma unroll
    for (int j=0;j<2;j++)
        boff[j] = (uint32_t)((wn*32 + j*16 + off16)*RPAD);

    const int nch = K >> 5;                      // BK = 32
    stage_load(sbase, A, Bw, m0, n0, K, 0, tid);
    if (nch > 1)
        stage_load(sbase + STG, A, Bw, m0, n0, K, 32, tid);

    int st = 0;
    for (int kc=0; kc<nch; kc++){
        if (kc+2 < nch){
            int ps = st+2; if (ps >= NSTAGE) ps -= NSTAGE;
            stage_load(sbase + ps*STG, A, Bw, m0, n0, K, (kc+2)*32, tid);
            asm volatile("cp.async.wait_group 2;" ::: "memory");
        } else if (kc+1 < nch){
            asm volatile("cp.async.wait_group 1;" ::: "memory");
        } else {
            asm volatile("cp.async.wait_group 0;" ::: "memory");
        }
        __syncthreads();

        const uint32_t sb = sbase + st*STG;
        #pragma unroll
        for (int kk=0; kk<2; kk++){              // 2 k16 steps per BK=32
            const uint32_t cb = (uint32_t)((kk*2 + khalf)*16);
            uint32_t ah[4][4];
            #pragma unroll
            for (int mi=0;mi<4;mi++)
                ldsm_x4(ah[mi], sb + aoff[mi] + cb);
            #pragma unroll
            for (int j=0;j<2;j++){
                uint32_t bh[4];
                ldsm_x4(bh, sb + CH_A + boff[j] + cb);
                #pragma unroll
                for (int mi=0;mi<4;mi++){
                    mma16816(acc[mi][j*2+0], ah[mi], bh[0], bh[2]);
                    mma16816(acc[mi][j*2+1], ah[mi], bh[1], bh[3]);
                }
            }
        }
        __syncthreads();
        if (++st == NSTAGE) st = 0;
    }

    // ---- epilogue ----
    #pragma unroll
    for (int mi=0;mi<4;mi++){
        const int r0 = m0 + wm*64 + mi*16 + (lane>>2);
        #pragma unroll
        for (int nj=0;nj<4;nj++){
            const int c = n0 + wn*32 + nj*8 + (lane&3)*2;
            const float b0 = bias[c], b1 = bias[c+1];
            #pragma unroll
            for (int half=0; half<2; half++){
                const int row = r0 + half*8;
                float v0 = acc[mi][nj][half*2+0] + b0;
                float v1 = acc[mi][nj][half*2+1] + b1;
                if (EPI == 0){
                    const int qi   = c / CDIM;
                    const int rem  = c - qi*CDIM;
                    const int head = rem / HD, hd = rem - head*HD;
                    const int win  = row >> 6, tok = row & 63;
                    const size_t dst = (((size_t)win*HEADS + head)*NTOK + tok)*HD + hd;
                    if (qi==0){      o0[dst] = v0*QSCALE; o0[dst+1] = v1*QSCALE; }
                    else if (qi==1){ o1[dst] = v0;        o1[dst+1] = v1; }
                    else{            o2[dst] = v0;        o2[dst+1] = v1; }
                } else if (EPI == 1){
                    const size_t idx = (size_t)row*Ncols + c;
                    o0[idx]   = v0;
                    o0[idx+1] = v1;
                } else if (EPI == 2){
                    const size_t idx = (size_t)row*Ncols + c;
                    const float g0 = 0.5f*v0*(1.f + erff(v0*0.70710678118654752f));
                    const float g1 = 0.5f*v1*(1.f + erff(v1*0.70710678118654752f));
                    __half2 t2; t2.x = __float2half_rn(g0); t2.y = __float2half_rn(g1);
                    *reinterpret_cast<__half2*>((__half*)o0 + idx) = t2;
                } else {
                    const size_t idx = (size_t)row*Ncols + c;
                    o0[idx]   = res[idx]   + v0;
                    o0[idx+1] = res[idx+1] + v1;
                }
            }
        }
    }
}

// ============ kernel 3: windowed attention, one block per (window, head) ============
__global__ void __launch_bounds__(64) attn_kernel(const float* __restrict__ rpb)
{
    __shared__ float sk[NTOK*HD];
    __shared__ float sv[NTOK*HD];
    __shared__ float srp[225];
    __shared__ float Ss[NTOK*64];
    const int blk = blockIdx.x;
    const int win = blk >> 3, head = blk & 7;
    const int tid = threadIdx.x;
    const size_t base = (size_t)blk * (NTOK*HD);
    for (int i=tid;i<NTOK*HD;i+=64){ sk[i]=g_k[base+i]; sv[i]=g_v[base+i]; }
    for (int i=tid;i<225;i+=64) srp[i] = rpb[(size_t)i*HEADS + head];

    float qreg[24];
    {
        const float4* qp = reinterpret_cast<const float4*>(&g_q[base + (size_t)tid*HD]);
        #pragma unroll
        for (int i=0;i<6;i++){
            float4 t = qp[i];
            qreg[4*i]=t.x; qreg[4*i+1]=t.y; qreg[4*i+2]=t.z; qreg[4*i+3]=t.w;
        }
    }
    __syncthreads();

    const int wrow = (win & (NW-1)) >> 5;
    const int wcol = win & 31;
    const int r1 = tid >> 3, c1 = tid & 7;

    float mx = -1e30f;
    #pragma unroll 4
    for (int m=0;m<NTOK;m++){
        float s = 0.f;
        #pragma unroll
        for (int d=0;d<24;d++) s += qreg[d]*sk[m*24+d];
        const int r2 = m>>3, c2 = m&7;
        s += srp[(r1-r2+7)*15 + (c1-c2+7)];
        const bool masked = (wrow==31 && ((r1>>2)!=(r2>>2))) ||
                            (wcol==31 && ((c1>>2)!=(c2>>2)));
        if (masked) s -= 100.f;
        Ss[m*64+tid] = s;
        mx = fmaxf(mx, s);
    }
    float sum = 0.f;
    #pragma unroll 4
    for (int m=0;m<NTOK;m++){
        float e = __expf(Ss[m*64+tid] - mx);
        Ss[m*64+tid] = e;
        sum += e;
    }
    const float inv = 1.f/sum;
    float o[24];
    #pragma unroll
    for (int d=0;d<24;d++) o[d]=0.f;
    #pragma unroll 4
    for (int m=0;m<NTOK;m++){
        const float p = Ss[m*64+tid]*inv;
        #pragma unroll
        for (int d=0;d<24;d++) o[d] += p*sv[m*24+d];
    }
    const size_t ob = ((size_t)win*NTOK + tid)*CDIM + head*HD;
    #pragma unroll
    for (int i=0;i<12;i++){
        __half2 t2;
        t2.x = __float2half_rn(o[2*i]);
        t2.y = __float2half_rn(o[2*i+1]);
        *reinterpret_cast<__half2*>(&g_att[ob + 2*i]) = t2;
    }
}

// ============ kernel 5: window reverse + roll(+4,+4) + residual + LN2 ============
__global__ void __launch_bounds__(128) postattn_kernel(
    const float* __restrict__ x, const float* __restrict__ g, const float* __restrict__ b)
{
    extern __shared__ float s[];
    float* sg = s + CDIM*128;
    float* sb = sg + CDIM;
    const int tid = threadIdx.x;
    const int w0 = blockIdx.x*128, h = blockIdx.y, bb = blockIdx.z;
    for (int i=tid;i<CDIM;i+=128){ sg[i]=g[i]; sb[i]=b[i]; }
    const float* xp = x + (size_t)bb*CDIM*HIMG*WIMG + (size_t)h*WIMG + w0;
    #pragma unroll 4
    for (int c=0;c<CDIM;c++) s[c*128+tid] = xp[(size_t)c*(HIMG*WIMG)+tid];
    __syncthreads();
    const int w  = w0 + tid;
    const int hr = (h-4)&255, wr = (w-4)&255;
    const int win = bb*NW + (hr>>3)*NWX + (wr>>3);
    const size_t pbase = ((size_t)win*NTOK + ((hr&7)<<3) + (wr&7))*CDIM;
    float sum=0.f, sq=0.f;
    for (int c=0;c<CDIM;c++){
        float v = s[c*128+tid] + g_proj[pbase+c];
        s[c*128+tid] = v; sum += v; sq += v*v;
    }
    const float mean = sum*(1.f/CDIM);
    const float var  = sq*(1.f/CDIM) - mean*mean;
    const float rstd = rsqrtf(var + LN_EPS);
    const size_t ob = (((size_t)bb*HIMG + h)*WIMG + w)*CDIM;
    for (int c=0;c<CDIM;c++){
        const float v = s[c*128+tid];
        g_xh[ob+c] = v;
        g_h2[ob+c] = __float2half_rn((v-mean)*rstd*sg[c] + sb[c]);
    }
}

// ============ kernel 8: BHWC -> BCHW output transpose ============
__global__ void out_transpose_kernel(float* __restrict__ out)
{
    __shared__ float t[32][33];
    const int tx = threadIdx.x, ty = threadIdx.y;   // (32, 8)
    const int w0 = blockIdx.x*32, h = blockIdx.y, bb = blockIdx.z;
    const size_t trow = ((size_t)bb*HIMG + h)*WIMG + w0;
    for (int c0=0;c0<CDIM;c0+=32){
        #pragma unroll
        for (int j=0;j<4;j++){
            int wl = ty + j*8;
            t[wl][tx] = g_y[(trow+wl)*CDIM + c0 + tx];
        }
        __syncthreads();
        #pragma unroll
        for (int j=0;j<4;j++){
            int cl = ty + j*8;
            out[(((size_t)bb*CDIM + c0+cl)*HIMG + h)*WIMG + w0 + tx] = t[tx][cl];
        }
        __syncthreads();
    }
}

// ============ launch ============
extern "C" void kernel_launch(void* const* d_in, const int* in_sizes, int n_in,
                              void* d_out, int out_size)
{
    (void)in_sizes; (void)n_in; (void)out_size;
    const float* x      = (const float*)d_in[0];
    const float* n1g    = (const float*)d_in[1];
    const float* n1b    = (const float*)d_in[2];
    const float* qkv_w  = (const float*)d_in[3];
    const float* qkv_b  = (const float*)d_in[4];
    const float* proj_w = (const float*)d_in[5];
    const float* proj_b = (const float*)d_in[6];
    const float* rpb    = (const float*)d_in[7];
    const float* n2g    = (const float*)d_in[8];
    const float* n2b    = (const float*)d_in[9];
    const float* fc1_w  = (const float*)d_in[10];
    const float* fc1_b  = (const float*)d_in[11];
    const float* fc2_w  = (const float*)d_in[12];
    const float* fc2_b  = (const float*)d_in[13];
    float* out = (float*)d_out;

    __half *hw,*at,*h2,*md,*wq,*wp,*w1,*w2;
    float *q,*k,*v,*proj,*xh,*y;
    cudaGetSymbolAddress((void**)&hw,  g_hwin);
    cudaGetSymbolAddress((void**)&q,   g_q);
    cudaGetSymbolAddress((void**)&k,   g_k);
    cudaGetSymbolAddress((void**)&v,   g_v);
    cudaGetSymbolAddress((void**)&at,  g_att);
    cudaGetSymbolAddress((void**)&proj,g_proj);
    cudaGetSymbolAddress((void**)&xh,  g_xh);
    cudaGetSymbolAddress((void**)&h2,  g_h2);
    cudaGetSymbolAddress((void**)&md,  g_mid);
    cudaGetSymbolAddress((void**)&y,   g_y);
    cudaGetSymbolAddress((void**)&wq,  g_wqkv);
    cudaGetSymbolAddress((void**)&wp,  g_wprj);
    cudaGetSymbolAddress((void**)&w1,  g_wfc1);
    cudaGetSymbolAddress((void**)&w2,  g_wfc2);

    cudaFuncSetAttribute(ln1_partition_kernel,
        cudaFuncAttributeMaxDynamicSharedMemorySize, LN_SMEM_BYTES);
    cudaFuncSetAttribute(postattn_kernel,
        cudaFuncAttributeMaxDynamicSharedMemorySize, LN_SMEM_BYTES);
    cudaFuncSetAttribute(mma_gemm<0>,
        cudaFuncAttributeMaxDynamicSharedMemorySize, SMEM_MMA);
    cudaFuncSetAttribute(mma_gemm<1>,
        cudaFuncAttributeMaxDynamicSharedMemorySize, SMEM_MMA);
    cudaFuncSetAttribute(mma_gemm<2>,
        cudaFuncAttributeMaxDynamicSharedMemorySize, SMEM_MMA);
    cudaFuncSetAttribute(mma_gemm<3>,
        cudaFuncAttributeMaxDynamicSharedMemorySize, SMEM_MMA);

    const dim3 wt(32,8);
    // 0. pre-transpose weights to [N][K] fp16
    wtrans_kernel<<<dim3(576/32, 192/32), wt>>>(qkv_w, wq, CDIM, 3*CDIM);
    wtrans_kernel<<<dim3(192/32, 192/32), wt>>>(proj_w, wp, CDIM, CDIM);
    wtrans_kernel<<<dim3(768/32, 192/32), wt>>>(fc1_w, w1, CDIM, CMID);
    wtrans_kernel<<<dim3(192/32, 768/32), wt>>>(fc2_w, w2, CMID, CDIM);

    const dim3 lnGrid(WIMG/128, HIMG, BATCH);

    // 1. LN1 + roll + window partition (fp16)
    ln1_partition_kernel<<<lnGrid, 128, LN_SMEM_BYTES>>>(x, n1g, n1b);

    // 2. qkv GEMM: (262144 x 192) @ (192 x 576), split q/k/v, q pre-scaled
    mma_gemm<0><<<dim3(9, TPIX/256), 256, SMEM_MMA>>>(
        hw, wq, qkv_b, q, k, v, nullptr, CDIM, 3*CDIM);

    // 3. attention per (window, head) -> fp16
    attn_kernel<<<BWIN*HEADS, 64>>>(rpb);

    // 4. proj GEMM: (262144 x 192) @ (192 x 192)
    mma_gemm<1><<<dim3(3, TPIX/256), 256, SMEM_MMA>>>(
        at, wp, proj_b, proj, nullptr, nullptr, nullptr, CDIM, CDIM);

    // 5. window reverse + roll + residual + LN2 (h2 as fp16)
    postattn_kernel<<<lnGrid, 128, LN_SMEM_BYTES>>>(x, n2g, n2b);

    // 6. fc1 GEMM: (262144 x 192) @ (192 x 768) + GELU -> fp16
    mma_gemm<2><<<dim3(12, TPIX/256), 256, SMEM_MMA>>>(
        h2, w1, fc1_b, (float*)md, nullptr, nullptr, nullptr, CDIM, CMID);

    // 7. fc2 GEMM: (262144 x 768) @ (768 x 192) + residual
    mma_gemm<3><<<dim3(3, TPIX/256), 256, SMEM_MMA>>>(
        md, w2, fc2_b, y, nullptr, nullptr, xh, CMID, CDIM);

    // 8. BHWC -> BCHW
    out_transpose_kernel<<<dim3(WIMG/32, HIMG, BATCH), dim3(32,8)>>>(out);
}

// round 16
// speedup vs baseline: 1.4286x; 1.4261x over previous
#include <cuda_runtime.h>
#include <cuda_fp16.h>
#include <math.h>
#include <stdint.h>

// ---------------- problem constants ----------------
#define CDIM   192
#define HEADS  8
#define HD     24
#define NTOK   64
#define BATCH  4
#define HIMG   256
#define WIMG   256
#define NWX    32
#define NW     1024
#define BWIN   4096
#define TPIX   262144
#define CMID   768
#define QSCALE 0.20412414523193154f
#define LN_EPS 1e-5f

// [c][pix] staging with pitch 129 words -> conflict-free column reads
#define LNPITCH 129
#define LN_SMEM_BYTES ((CDIM*LNPITCH + 2*CDIM)*4)   // 100608 B

// ---------------- scratch ----------------
__device__ __half g_hwin[(size_t)TPIX*CDIM];
__device__ __half g_q[(size_t)BWIN*HEADS*NTOK*HD];
__device__ __half g_k[(size_t)BWIN*HEADS*NTOK*HD];
__device__ __half g_v[(size_t)BWIN*HEADS*NTOK*HD];
__device__ __half g_att[(size_t)TPIX*CDIM];
__device__ __half g_proj[(size_t)TPIX*CDIM];        // PIXEL order (roll already applied)
__device__ float g_xh[(size_t)TPIX*CDIM];           // pixel order
__device__ __half g_h2[(size_t)TPIX*CDIM];          // pixel order
__device__ __half g_mid[(size_t)TPIX*CMID];
__device__ float g_y[(size_t)TPIX*CDIM];

// transposed weights [N][K], fp16
__device__ __half g_wqkv[576*192];
__device__ __half g_wprj[192*192];
__device__ __half g_wfc1[768*192];
__device__ __half g_wfc2[192*768];

// ---------------- helpers ----------------
__device__ __forceinline__ uint32_t smem_u32(const void* p){
    uint32_t a;
    asm("{ .reg .u64 t; cvta.to.shared.u64 t, %1; cvt.u32.u64 %0, t; }" : "=r"(a) : "l"(p));
    return a;
}
__device__ __forceinline__ void cp_async16(uint32_t dst, const void* src){
    asm volatile("cp.async.cg.shared.global [%0], [%1], 16;" :: "r"(dst), "l"(src));
}
__device__ __forceinline__ void ldsm_x4(uint32_t* r, uint32_t addr){
    asm volatile("ldmatrix.sync.aligned.m8n8.x4.shared.b16 {%0,%1,%2,%3}, [%4];"
        : "=r"(r[0]), "=r"(r[1]), "=r"(r[2]), "=r"(r[3]) : "r"(addr));
}
__device__ __forceinline__ void mma16816(float* d, const uint32_t* a,
                                         uint32_t b0, uint32_t b1){
    asm volatile("mma.sync.aligned.m16n8k16.row.col.f32.f16.f16.f32 "
        "{%0,%1,%2,%3}, {%4,%5,%6,%7}, {%8,%9}, {%0,%1,%2,%3};"
        : "+f"(d[0]), "+f"(d[1]), "+f"(d[2]), "+f"(d[3])
        : "r"(a[0]), "r"(a[1]), "r"(a[2]), "r"(a[3]), "r"(b0), "r"(b1));
}

// ============ weight transpose: w[K][N] fp32 -> wh[N][K] fp16 ============
__global__ void wtrans_kernel(const float* __restrict__ w,
    __half* __restrict__ wh, int K, int N)
{
    __shared__ float t[32][33];
    const int tx = threadIdx.x, ty = threadIdx.y;   // (32, 8)
    const int n0 = blockIdx.x*32, k0 = blockIdx.y*32;
    #pragma unroll
    for (int j=0;j<4;j++)
        t[ty+8*j][tx] = w[(size_t)(k0+ty+8*j)*N + n0 + tx];
    __syncthreads();
    #pragma unroll
    for (int j=0;j<4;j++){
        const int n = ty + 8*j;
        wh[(size_t)(n0+n)*K + k0 + tx] = __float2half_rn(t[tx][n]);
    }
}

// ============ kernel 1: LN1 + roll(-4,-4) + window partition (fp16, coalesced) ============
__global__ void __launch_bounds__(128) ln1_partition_kernel(
    const float* __restrict__ x, const float* __restrict__ g, const float* __restrict__ b)
{
    extern __shared__ float s[];
    float* sg = s + CDIM*LNPITCH;
    float* sb = sg + CDIM;
    const int tid = threadIdx.x;
    const int lane = tid & 31, wid = tid >> 5;
    const int w0 = blockIdx.x*128, h = blockIdx.y, bb = blockIdx.z;
    for (int i = tid; i < CDIM; i += 128){ sg[i]=g[i]; sb[i]=b[i]; }
    const float* xp = x + (size_t)bb*CDIM*HIMG*WIMG + (size_t)h*WIMG + w0;
    #pragma unroll 4
    for (int c=0;c<CDIM;c++) s[c*LNPITCH+tid] = xp[(size_t)c*(HIMG*WIMG)+tid];
    __syncthreads();

    const int hr = (h-4)&255;
    // warp-per-pixel: reduce + normalize + coalesced fp16 store in window order
    for (int p = wid*32; p < wid*32+32; p++){
        float vv[6];
        float a1 = 0.f, a2 = 0.f;
        #pragma unroll
        for (int cc=0; cc<6; cc++){
            const float v = s[(cc*32+lane)*LNPITCH + p];
            vv[cc] = v; a1 += v; a2 += v*v;
        }
        #pragma unroll
        for (int o=16; o; o>>=1){
            a1 += __shfl_xor_sync(0xffffffffu, a1, o);
            a2 += __shfl_xor_sync(0xffffffffu, a2, o);
        }
        const float mean = a1*(1.f/CDIM);
        const float var  = a2*(1.f/CDIM) - mean*mean;
        const float rstd = rsqrtf(var + LN_EPS);
        const int w  = w0 + p;
        const int wr = (w-4)&255;
        const int win = bb*NW + (hr>>3)*NWX + (wr>>3);
        const size_t rowb = ((size_t)win*NTOK + ((hr&7)<<3) + (wr&7))*CDIM;
        #pragma unroll
        for (int cc=0; cc<6; cc++){
            const int c = cc*32 + lane;
            g_hwin[rowb + c] = __float2half_rn((vv[cc]-mean)*rstd*sg[c] + sb[c]);
        }
    }
}

// ============ HMMA fp16 GEMM, block 256x64, BK=32, warp tile 64x32 ============
#define RPAD 80
#define CH_A (256*RPAD)
#define CH_B (64*RPAD)
#define STG  (CH_A + CH_B)
#define NSTAGE 3
#define SMEM_MMA (NSTAGE*STG)      // 76800 B

__device__ __forceinline__ void stage_load(uint32_t sb,
    const __half* __restrict__ A, const __half* __restrict__ Bw,
    int m0, int n0, int K, int k0, int tid)
{
    #pragma unroll
    for (int i=0;i<4;i++){
        const int cid = tid + i*256;
        const int row = cid>>2, c = cid&3;
        const uint32_t off = (uint32_t)(row*RPAD + c*16);
        cp_async16(sb + off, A + (size_t)(m0+row)*K + k0 + c*8);
    }
    {
        const int row = tid>>2, c = tid&3;
        const uint32_t off = (uint32_t)(row*RPAD + c*16);
        cp_async16(sb + CH_A + off, Bw + (size_t)(n0+row)*K + k0 + c*8);
    }
    asm volatile("cp.async.commit_group;" ::: "memory");
}

// EPI: 0 = qkv split fp16 (+q scale), 2 = GELU -> fp16, 3 = residual add fp32,
//      4 = fp16 out in PIXEL order (inverse roll; proj)
template<int EPI>
__global__ void __launch_bounds__(256,2) mma_gemm(
    const __half* __restrict__ A, const __half* __restrict__ Bw,
    const float* __restrict__ bias,
    float* __restrict__ o0, float* __restrict__ o1, float* __restrict__ o2,
    const float* __restrict__ res, int K, int Ncols)
{
    extern __shared__ __align__(16) char dsm[];
    const uint32_t sbase = smem_u32(dsm);
    const int tid = threadIdx.x;
    const int wid = tid >> 5, lane = tid & 31;
    const int wm = wid >> 1, wn = wid & 1;
    const int m0 = blockIdx.y * 256;
    const int n0 = blockIdx.x * 64;

    float acc[4][4][4];
    #pragma unroll
    for (int mi=0;mi<4;mi++)
        #pragma unroll
        for (int nj=0;nj<4;nj++)
            #pragma unroll
            for (int e=0;e<4;e++) acc[mi][nj][e]=0.f;

    const int off16 = lane & 15;
    const int khalf = lane >> 4;
    uint32_t aoff[4], boff[2];
    #pragma unroll
    for (int mi=0;mi<4;mi++)
        aoff[mi] = (uint32_t)((wm*64 + mi*16 + off16)*RPAD);
    #pragma unroll
    for (int j=0;j<2;j++)
        boff[j] = (uint32_t)((wn*32 + j*16 + off16)*RPAD);

    const int nch = K >> 5;
    stage_load(sbase, A, Bw, m0, n0, K, 0, tid);
    if (nch > 1)
        stage_load(sbase + STG, A, Bw, m0, n0, K, 32, tid);

    int st = 0;
    for (int kc=0; kc<nch; kc++){
        if (kc+2 < nch){
            int ps = st+2; if (ps >= NSTAGE) ps -= NSTAGE;
            stage_load(sbase + ps*STG, A, Bw, m0, n0, K, (kc+2)*32, tid);
            asm volatile("cp.async.wait_group 2;" ::: "memory");
        } else if (kc+1 < nch){
            asm volatile("cp.async.wait_group 1;" ::: "memory");
        } else {
            asm volatile("cp.async.wait_group 0;" ::: "memory");
        }
        __syncthreads();

        const uint32_t sb = sbase + st*STG;
        #pragma unroll
        for (int kk=0; kk<2; kk++){
            const uint32_t cb = (uint32_t)((kk*2 + khalf)*16);
            uint32_t ah[4][4];
            #pragma unroll
            for (int mi=0;mi<4;mi++)
                ldsm_x4(ah[mi], sb + aoff[mi] + cb);
            #pragma unroll
            for (int j=0;j<2;j++){
                uint32_t bh[4];
                ldsm_x4(bh, sb + CH_A + boff[j] + cb);
                #pragma unroll
                for (int mi=0;mi<4;mi++){
                    mma16816(acc[mi][j*2+0], ah[mi], bh[0], bh[2]);
                    mma16816(acc[mi][j*2+1], ah[mi], bh[1], bh[3]);
                }
            }
        }
        __syncthreads();
        if (++st == NSTAGE) st = 0;
    }

    // ---- epilogue ----
    #pragma unroll
    for (int mi=0;mi<4;mi++){
        const int r0 = m0 + wm*64 + mi*16 + (lane>>2);
        #pragma unroll
        for (int nj=0;nj<4;nj++){
            const int c = n0 + wn*32 + nj*8 + (lane&3)*2;
            const float b0 = bias[c], b1 = bias[c+1];
            #pragma unroll
            for (int half=0; half<2; half++){
                const int row = r0 + half*8;
                float v0 = acc[mi][nj][half*2+0] + b0;
                float v1 = acc[mi][nj][half*2+1] + b1;
                if (EPI == 0){
                    const int qi   = c / CDIM;
                    const int rem  = c - qi*CDIM;
                    const int head = rem / HD, hd = rem - head*HD;
                    const int win  = row >> 6, tok = row & 63;
                    const size_t dst = (((size_t)win*HEADS + head)*NTOK + tok)*HD + hd;
                    __half2 t2;
                    if (qi==0){
                        t2.x = __float2half_rn(v0*QSCALE);
                        t2.y = __float2half_rn(v1*QSCALE);
                        *reinterpret_cast<__half2*>((__half*)o0 + dst) = t2;
                    } else if (qi==1){
                        t2.x = __float2half_rn(v0); t2.y = __float2half_rn(v1);
                        *reinterpret_cast<__half2*>((__half*)o1 + dst) = t2;
                    } else {
                        t2.x = __float2half_rn(v0); t2.y = __float2half_rn(v1);
                        *reinterpret_cast<__half2*>((__half*)o2 + dst) = t2;
                    }
                } else if (EPI == 2){
                    const size_t idx = (size_t)row*Ncols + c;
                    const float g0 = 0.5f*v0*(1.f + erff(v0*0.70710678118654752f));
                    const float g1 = 0.5f*v1*(1.f + erff(v1*0.70710678118654752f));
                    __half2 t2; t2.x = __float2half_rn(g0); t2.y = __float2half_rn(g1);
                    *reinterpret_cast<__half2*>((__half*)o0 + idx) = t2;
                } else if (EPI == 3){
                    const size_t idx = (size_t)row*Ncols + c;
                    o0[idx]   = res[idx]   + v0;
                    o0[idx+1] = res[idx+1] + v1;
                } else {   // EPI == 4: proj -> fp16, pixel order (inverse roll)
                    const int wb = row >> 6;
                    const int bsel = wb >> 10;
                    const int wl = wb & (NW-1);
                    const int tok = row & 63;
                    const int hr = ((wl >> 5) << 3) + (tok >> 3);
                    const int wr = ((wl & 31) << 3) + (tok & 7);
                    const int hh = (hr + 4) & 255, ww = (wr + 4) & 255;
                    const size_t pix = ((size_t)bsel*HIMG + hh)*WIMG + ww;
                    __half2 t2; t2.x = __float2half_rn(v0); t2.y = __float2half_rn(v1);
                    *reinterpret_cast<__half2*>((__half*)o0 + pix*CDIM + c) = t2;
                }
            }
        }
    }
}

// ============ kernel 3: windowed attention, one block per (window, head) ============
__global__ void __launch_bounds__(64) attn_kernel(const float* __restrict__ rpb)
{
    __shared__ float sk[NTOK*HD];
    __shared__ float sv[NTOK*HD];
    __shared__ float srp[225];
    __shared__ float Ss[NTOK*64];
    const int blk = blockIdx.x;
    const int win = blk >> 3, head = blk & 7;
    const int tid = threadIdx.x;
    const size_t base = (size_t)blk * (NTOK*HD);
    {
        const __half2* kp = reinterpret_cast<const __half2*>(g_k + base);
        const __half2* vp = reinterpret_cast<const __half2*>(g_v + base);
        for (int i=tid;i<NTOK*HD/2;i+=64){
            float2 f = __half22float2(kp[i]);
            sk[2*i] = f.x; sk[2*i+1] = f.y;
            float2 g2 = __half22float2(vp[i]);
            sv[2*i] = g2.x; sv[2*i+1] = g2.y;
        }
    }
    for (int i=tid;i<225;i+=64) srp[i] = rpb[(size_t)i*HEADS + head];

    float qreg[24];
    {
        const __half2* qp = reinterpret_cast<const __half2*>(g_q + base + (size_t)tid*HD);
        #pragma unroll
        for (int i=0;i<12;i++){
            float2 f = __half22float2(qp[i]);
            qreg[2*i] = f.x; qreg[2*i+1] = f.y;
        }
    }
    __syncthreads();

    const int wrow = (win & (NW-1)) >> 5;
    const int wcol = win & 31;
    const int r1 = tid >> 3, c1 = tid & 7;

    float mx = -1e30f;
    #pragma unroll 4
    for (int m=0;m<NTOK;m++){
        float s = 0.f;
        #pragma unroll
        for (int d=0;d<24;d++) s += qreg[d]*sk[m*24+d];
        const int r2 = m>>3, c2 = m&7;
        s += srp[(r1-r2+7)*15 + (c1-c2+7)];
        const bool masked = (wrow==31 && ((r1>>2)!=(r2>>2))) ||
                            (wcol==31 && ((c1>>2)!=(c2>>2)));
        if (masked) s -= 100.f;
        Ss[m*64+tid] = s;
        mx = fmaxf(mx, s);
    }
    float sum = 0.f;
    #pragma unroll 4
    for (int m=0;m<NTOK;m++){
        float e = __expf(Ss[m*64+tid] - mx);
        Ss[m*64+tid] = e;
        sum += e;
    }
    const float inv = 1.f/sum;
    float o[24];
    #pragma unroll
    for (int d=0;d<24;d++) o[d]=0.f;
    #pragma unroll 4
    for (int m=0;m<NTOK;m++){
        const float p = Ss[m*64+tid]*inv;
        #pragma unroll
        for (int d=0;d<24;d++) o[d] += p*sv[m*24+d];
    }
    const size_t ob = ((size_t)win*NTOK + tid)*CDIM + head*HD;
    #pragma unroll
    for (int i=0;i<12;i++){
        __half2 t2;
        t2.x = __float2half_rn(o[2*i]);
        t2.y = __float2half_rn(o[2*i+1]);
        *reinterpret_cast<__half2*>(&g_att[ob + 2*i]) = t2;
    }
}

// ============ kernel 5: residual + LN2 (proj already pixel-order fp16) ============
__global__ void __launch_bounds__(128) postattn_kernel(
    const float* __restrict__ x, const float* __restrict__ g, const float* __restrict__ b)
{
    extern __shared__ float s[];
    float* sg = s + CDIM*LNPITCH;
    float* sb = sg + CDIM;
    const int tid = threadIdx.x;
    const int lane = tid & 31, wid = tid >> 5;
    const int w0 = blockIdx.x*128, h = blockIdx.y, bb = blockIdx.z;
    for (int i=tid;i<CDIM;i+=128){ sg[i]=g[i]; sb[i]=b[i]; }
    const float* xp = x + (size_t)bb*CDIM*HIMG*WIMG + (size_t)h*WIMG + w0;
    #pragma unroll 4
    for (int c=0;c<CDIM;c++) s[c*LNPITCH+tid] = xp[(size_t)c*(HIMG*WIMG)+tid];
    __syncthreads();

    // warp-per-pixel: add proj, reduce, LN2, coalesced xh/h2 stores
    for (int p = wid*32; p < wid*32+32; p++){
        const size_t pix = ((size_t)bb*HIMG + h)*WIMG + w0 + p;
        const __half2* pr = reinterpret_cast<const __half2*>(g_proj + pix*CDIM);
        float vv[6];
        float a1 = 0.f, a2 = 0.f;
        #pragma unroll
        for (int cc=0; cc<3; cc++){
            const int c2 = cc*64 + 2*lane;
            const float2 f = __half22float2(pr[cc*32 + lane]);
            const float v0 = s[c2*LNPITCH + p]     + f.x;
            const float v1 = s[(c2+1)*LNPITCH + p] + f.y;
            vv[2*cc] = v0; vv[2*cc+1] = v1;
            a1 += v0 + v1; a2 += v0*v0 + v1*v1;
        }
        #pragma unroll
        for (int o=16; o; o>>=1){
            a1 += __shfl_xor_sync(0xffffffffu, a1, o);
            a2 += __shfl_xor_sync(0xffffffffu, a2, o);
        }
        const float mean = a1*(1.f/CDIM);
        const float var  = a2*(1.f/CDIM) - mean*mean;
        const float rstd = rsqrtf(var + LN_EPS);
        #pragma unroll
        for (int cc=0; cc<3; cc++){
            const int c2 = cc*64 + 2*lane;
            const float v0 = vv[2*cc], v1 = vv[2*cc+1];
            float2 xo; xo.x = v0; xo.y = v1;
            *reinterpret_cast<float2*>(&g_xh[pix*CDIM + c2]) = xo;
            __half2 t2;
            t2.x = __float2half_rn((v0-mean)*rstd*sg[c2]   + sb[c2]);
            t2.y = __float2half_rn((v1-mean)*rstd*sg[c2+1] + sb[c2+1]);
            *reinterpret_cast<__half2*>(&g_h2[pix*CDIM + c2]) = t2;
        }
    }
}

// ============ kernel 8: BHWC -> BCHW output transpose ============
__global__ void out_transpose_kernel(float* __restrict__ out)
{
    __shared__ float t[32][33];
    const int tx = threadIdx.x, ty = threadIdx.y;   // (32, 8)
    const int w0 = blockIdx.x*32, h = blockIdx.y, bb = blockIdx.z;
    const size_t trow = ((size_t)bb*HIMG + h)*WIMG + w0;
    for (int c0=0;c0<CDIM;c0+=32){
        #pragma unroll
        for (int j=0;j<4;j++){
            int wl = ty + j*8;
            t[wl][tx] = g_y[(trow+wl)*CDIM + c0 + tx];
        }
        __syncthreads();
        #pragma unroll
        for (int j=0;j<4;j++){
            int cl = ty + j*8;
            out[(((size_t)bb*CDIM + c0+cl)*HIMG + h)*WIMG + w0 + tx] = t[tx][cl];
        }
        __syncthreads();
    }
}

// ============ launch ============
extern "C" void kernel_launch(void* const* d_in, const int* in_sizes, int n_in,
                              void* d_out, int out_size)
{
    (void)in_sizes; (void)n_in; (void)out_size;
    const float* x      = (const float*)d_in[0];
    const float* n1g    = (const float*)d_in[1];
    const float* n1b    = (const float*)d_in[2];
    const float* qkv_w  = (const float*)d_in[3];
    const float* qkv_b  = (const float*)d_in[4];
    const float* proj_w = (const float*)d_in[5];
    const float* proj_b = (const float*)d_in[6];
    const float* rpb    = (const float*)d_in[7];
    const float* n2g    = (const float*)d_in[8];
    const float* n2b    = (const float*)d_in[9];
    const float* fc1_w  = (const float*)d_in[10];
    const float* fc1_b  = (const float*)d_in[11];
    const float* fc2_w  = (const float*)d_in[12];
    const float* fc2_b  = (const float*)d_in[13];
    float* out = (float*)d_out;

    __half *hw,*qh,*kh,*vh,*at,*pj,*h2,*md,*wq,*wp,*w1,*w2;
    float *xh,*y;
    cudaGetSymbolAddress((void**)&hw,  g_hwin);
    cudaGetSymbolAddress((void**)&qh,  g_q);
    cudaGetSymbolAddress((void**)&kh,  g_k);
    cudaGetSymbolAddress((void**)&vh,  g_v);
    cudaGetSymbolAddress((void**)&at,  g_att);
    cudaGetSymbolAddress((void**)&pj,  g_proj);
    cudaGetSymbolAddress((void**)&xh,  g_xh);
    cudaGetSymbolAddress((void**)&h2,  g_h2);
    cudaGetSymbolAddress((void**)&md,  g_mid);
    cudaGetSymbolAddress((void**)&y,   g_y);
    cudaGetSymbolAddress((void**)&wq,  g_wqkv);
    cudaGetSymbolAddress((void**)&wp,  g_wprj);
    cudaGetSymbolAddress((void**)&w1,  g_wfc1);
    cudaGetSymbolAddress((void**)&w2,  g_wfc2);

    cudaFuncSetAttribute(ln1_partition_kernel,
        cudaFuncAttributeMaxDynamicSharedMemorySize, LN_SMEM_BYTES);
    cudaFuncSetAttribute(postattn_kernel,
        cudaFuncAttributeMaxDynamicSharedMemorySize, LN_SMEM_BYTES);
    cudaFuncSetAttribute(mma_gemm<0>,
        cudaFuncAttributeMaxDynamicSharedMemorySize, SMEM_MMA);
    cudaFuncSetAttribute(mma_gemm<2>,
        cudaFuncAttributeMaxDynamicSharedMemorySize, SMEM_MMA);
    cudaFuncSetAttribute(mma_gemm<3>,
        cudaFuncAttributeMaxDynamicSharedMemorySize, SMEM_MMA);
    cudaFuncSetAttribute(mma_gemm<4>,
        cudaFuncAttributeMaxDynamicSharedMemorySize, SMEM_MMA);

    const dim3 wt(32,8);
    // 0. pre-transpose weights to [N][K] fp16
    wtrans_kernel<<<dim3(576/32, 192/32), wt>>>(qkv_w, wq, CDIM, 3*CDIM);
    wtrans_kernel<<<dim3(192/32, 192/32), wt>>>(proj_w, wp, CDIM, CDIM);
    wtrans_kernel<<<dim3(768/32, 192/32), wt>>>(fc1_w, w1, CDIM, CMID);
    wtrans_kernel<<<dim3(192/32, 768/32), wt>>>(fc2_w, w2, CMID, CDIM);

    const dim3 lnGrid(WIMG/128, HIMG, BATCH);

    // 1. LN1 + roll + window partition (fp16, coalesced)
    ln1_partition_kernel<<<lnGrid, 128, LN_SMEM_BYTES>>>(x, n1g, n1b);

    // 2. qkv GEMM: split q/k/v fp16, q pre-scaled
    mma_gemm<0><<<dim3(9, TPIX/256), 256, SMEM_MMA>>>(
        hw, wq, qkv_b, (float*)qh, (float*)kh, (float*)vh, nullptr, CDIM, 3*CDIM);

    // 3. attention per (window, head) -> fp16
    attn_kernel<<<BWIN*HEADS, 64>>>(rpb);

    // 4. proj GEMM -> fp16, pixel order
    mma_gemm<4><<<dim3(3, TPIX/256), 256, SMEM_MMA>>>(
        at, wp, proj_b, (float*)pj, nullptr, nullptr, nullptr, CDIM, CDIM);

    // 5. residual + LN2 (pixel order; h2 fp16)
    postattn_kernel<<<lnGrid, 128, LN_SMEM_BYTES>>>(x, n2g, n2b);

    // 6. fc1 GEMM + GELU -> fp16
    mma_gemm<2><<<dim3(12, TPIX/256), 256, SMEM_MMA>>>(
        h2, w1, fc1_b, (float*)md, nullptr, nullptr, nullptr, CDIM, CMID);

    // 7. fc2 GEMM + residual -> fp32
    mma_gemm<3><<<dim3(3, TPIX/256), 256, SMEM_MMA>>>(
        md, w2, fc2_b, y, nullptr, nullptr, xh, CMID, CDIM);

    // 8. BHWC -> BCHW
    out_transpose_kernel<<<dim3(WIMG/32, HIMG, BATCH), dim3(32,8)>>>(out);
}